// round 1
// baseline (speedup 1.0000x reference)
#include <cuda_runtime.h>
#include <math.h>

#define B_  8
#define S_  1024
#define DM  512
#define H_  8
#define DK  64
#define NROWS (B_ * S_)   // 8192

// Scratch (allocation-free rule: __device__ globals)
__device__ float g_Q[NROWS * DM];
__device__ float g_K[NROWS * DM];
__device__ float g_V[NROWS * DM];
__device__ float g_M[NROWS * DM];

// ---------------------------------------------------------------------------
// GEMM: C[M,N] = A[M,K] @ B[K,N] + bias[N].  M%64==0, N%64==0, K%32==0.
// 64x64 tile, BK=32, 256 threads, 4x4 microtile per thread.
// ---------------------------------------------------------------------------
__global__ __launch_bounds__(256) void gemm_bias_kernel(
    const float* __restrict__ A, const float* __restrict__ Bm,
    const float* __restrict__ bias, float* __restrict__ C,
    int M, int N, int K)
{
    __shared__ float As[32][65];   // [k][m], padded: transpose-store conflict-free
    __shared__ float Bs[32][68];   // [k][n], padded to keep float4 alignment

    const int tid = threadIdx.x;
    const int tx  = tid & 15;        // 0..15 -> n
    const int ty  = tid >> 4;        // 0..15 -> m
    const int bm0 = blockIdx.y * 64;
    const int bn0 = blockIdx.x * 64;

    float acc[4][4];
#pragma unroll
    for (int i = 0; i < 4; i++)
#pragma unroll
        for (int j = 0; j < 4; j++) acc[i][j] = 0.f;

    for (int k0 = 0; k0 < K; k0 += 32) {
        // Load A tile (64 rows x 32 k), transpose into As[k][m]
#pragma unroll
        for (int t = 0; t < 2; t++) {
            int f   = tid + t * 256;         // 0..511
            int row = f >> 3;                // 0..63
            int kq  = f & 7;                 // 0..7 (float4 index along k)
            float4 a = *(const float4*)&A[(size_t)(bm0 + row) * K + k0 + kq * 4];
            As[kq * 4 + 0][row] = a.x;
            As[kq * 4 + 1][row] = a.y;
            As[kq * 4 + 2][row] = a.z;
            As[kq * 4 + 3][row] = a.w;
        }
        // Load B tile (32 k x 64 n)
#pragma unroll
        for (int t = 0; t < 2; t++) {
            int f  = tid + t * 256;          // 0..511
            int kk = f >> 4;                 // 0..31
            int nq = f & 15;                 // 0..15
            *(float4*)&Bs[kk][nq * 4] =
                *(const float4*)&Bm[(size_t)(k0 + kk) * N + bn0 + nq * 4];
        }
        __syncthreads();

#pragma unroll
        for (int k = 0; k < 32; k++) {
            float a[4], b[4];
#pragma unroll
            for (int i = 0; i < 4; i++) a[i] = As[k][ty * 4 + i];
#pragma unroll
            for (int j = 0; j < 4; j++) b[j] = Bs[k][tx * 4 + j];
#pragma unroll
            for (int i = 0; i < 4; i++)
#pragma unroll
                for (int j = 0; j < 4; j++) acc[i][j] += a[i] * b[j];
        }
        __syncthreads();
    }

#pragma unroll
    for (int i = 0; i < 4; i++) {
        int row = bm0 + ty * 4 + i;
#pragma unroll
        for (int j = 0; j < 4; j++) {
            int col = bn0 + tx * 4 + j;
            C[(size_t)row * N + col] = acc[i][j] + bias[col];
        }
    }
}

// ---------------------------------------------------------------------------
// Attention per (b,h): out = softmax(Q K^T / sqrt(dk)) V
// Block: 64 query rows, 256 threads (16x16), online softmax, 16 key tiles.
// Dynamic smem: Qs[64][65], KVs[64][65], Ps[64][64]
// ---------------------------------------------------------------------------
#define QS_STRIDE 65
#define ATTN_SMEM_FLOATS (2 * 64 * QS_STRIDE + 64 * 64)
#define ATTN_SMEM_BYTES  (ATTN_SMEM_FLOATS * 4)

__global__ __launch_bounds__(256) void attn_kernel()
{
    extern __shared__ float sm[];
    float* Qs  = sm;                       // [64][65]
    float* KVs = sm + 64 * QS_STRIDE;      // [64][65]
    float* Ps  = sm + 2 * 64 * QS_STRIDE;  // [64][64]

    const int tid = threadIdx.x;
    const int tx  = tid & 15;
    const int ty  = tid >> 4;
    const int bh  = blockIdx.y;
    const int b   = bh / H_;
    const int h   = bh % H_;
    const int q0  = blockIdx.x * 64;
    const float scale = 0.125f;  // 1/sqrt(64)

    // Load Q tile: Qs[r][d] = Q[b*S + q0+r][h*64 + d]
#pragma unroll
    for (int t = 0; t < 4; t++) {
        int f = tid + t * 256;     // 0..1023
        int r = f >> 4;            // 0..63
        int c = (f & 15) * 4;      // 0..60
        float4 v = *(const float4*)&g_Q[(size_t)(b * S_ + q0 + r) * DM + h * DK + c];
        Qs[r * QS_STRIDE + c + 0] = v.x;
        Qs[r * QS_STRIDE + c + 1] = v.y;
        Qs[r * QS_STRIDE + c + 2] = v.z;
        Qs[r * QS_STRIDE + c + 3] = v.w;
    }

    float m_run[4], l_run[4], o_acc[4][4];
#pragma unroll
    for (int i = 0; i < 4; i++) {
        m_run[i] = -1e30f;
        l_run[i] = 0.f;
#pragma unroll
        for (int j = 0; j < 4; j++) o_acc[i][j] = 0.f;
    }

    for (int kt = 0; kt < S_ / 64; kt++) {
        const int t0 = kt * 64;
        // Load K tile into KVs
#pragma unroll
        for (int t = 0; t < 4; t++) {
            int f = tid + t * 256;
            int r = f >> 4;
            int c = (f & 15) * 4;
            float4 v = *(const float4*)&g_K[(size_t)(b * S_ + t0 + r) * DM + h * DK + c];
            KVs[r * QS_STRIDE + c + 0] = v.x;
            KVs[r * QS_STRIDE + c + 1] = v.y;
            KVs[r * QS_STRIDE + c + 2] = v.z;
            KVs[r * QS_STRIDE + c + 3] = v.w;
        }
        __syncthreads();

        // S = Q @ K^T (64x64x64 tile)
        float s[4][4];
#pragma unroll
        for (int i = 0; i < 4; i++)
#pragma unroll
            for (int j = 0; j < 4; j++) s[i][j] = 0.f;

#pragma unroll 8
        for (int d = 0; d < 64; d++) {
            float a[4], bb[4];
#pragma unroll
            for (int i = 0; i < 4; i++) a[i]  = Qs[(ty * 4 + i) * QS_STRIDE + d];
#pragma unroll
            for (int j = 0; j < 4; j++) bb[j] = KVs[(tx * 4 + j) * QS_STRIDE + d];
#pragma unroll
            for (int i = 0; i < 4; i++)
#pragma unroll
                for (int j = 0; j < 4; j++) s[i][j] += a[i] * bb[j];
        }

        // Online softmax update (rows owned redundantly by the 16 tx-lanes of each ty)
#pragma unroll
        for (int i = 0; i < 4; i++) {
            float mx = -1e30f;
#pragma unroll
            for (int j = 0; j < 4; j++) {
                s[i][j] *= scale;
                mx = fmaxf(mx, s[i][j]);
            }
#pragma unroll
            for (int o = 8; o > 0; o >>= 1)
                mx = fmaxf(mx, __shfl_xor_sync(0xffffffffu, mx, o));
            float mnew  = fmaxf(m_run[i], mx);
            float alpha = __expf(m_run[i] - mnew);
            m_run[i] = mnew;
            float rs = 0.f;
#pragma unroll
            for (int j = 0; j < 4; j++) {
                float p = __expf(s[i][j] - mnew);
                s[i][j] = p;
                rs += p;
            }
#pragma unroll
            for (int o = 8; o > 0; o >>= 1)
                rs += __shfl_xor_sync(0xffffffffu, rs, o);
            l_run[i] = l_run[i] * alpha + rs;
#pragma unroll
            for (int j = 0; j < 4; j++) {
                o_acc[i][j] *= alpha;
                Ps[(ty * 4 + i) * 64 + tx * 4 + j] = s[i][j];
            }
        }
        __syncthreads();   // Ps complete; K reads done

        // Load V tile into KVs (reuse)
#pragma unroll
        for (int t = 0; t < 4; t++) {
            int f = tid + t * 256;
            int r = f >> 4;
            int c = (f & 15) * 4;
            float4 v = *(const float4*)&g_V[(size_t)(b * S_ + t0 + r) * DM + h * DK + c];
            KVs[r * QS_STRIDE + c + 0] = v.x;
            KVs[r * QS_STRIDE + c + 1] = v.y;
            KVs[r * QS_STRIDE + c + 2] = v.z;
            KVs[r * QS_STRIDE + c + 3] = v.w;
        }
        __syncthreads();

        // O += P @ V (64x64x64 tile)
#pragma unroll 8
        for (int t = 0; t < 64; t++) {
            float pv[4], vv[4];
#pragma unroll
            for (int i = 0; i < 4; i++) pv[i] = Ps[(ty * 4 + i) * 64 + t];
#pragma unroll
            for (int j = 0; j < 4; j++) vv[j] = KVs[t * QS_STRIDE + tx * 4 + j];
#pragma unroll
            for (int i = 0; i < 4; i++)
#pragma unroll
                for (int j = 0; j < 4; j++) o_acc[i][j] += pv[i] * vv[j];
        }
        __syncthreads();   // protect KVs/Ps for next tile
    }

    // Normalize and write msgs[b*S + q][h*64 + d]
#pragma unroll
    for (int i = 0; i < 4; i++) {
        float inv = 1.f / l_run[i];
        int row = b * S_ + q0 + ty * 4 + i;
#pragma unroll
        for (int j = 0; j < 4; j++)
            g_M[(size_t)row * DM + h * DK + tx * 4 + j] = o_acc[i][j] * inv;
    }
}

// ---------------------------------------------------------------------------
extern "C" void kernel_launch(void* const* d_in, const int* in_sizes, int n_in,
                              void* d_out, int out_size)
{
    const float* nodes = (const float*)d_in[0];
    const float* Wq    = (const float*)d_in[1];
    const float* Wk    = (const float*)d_in[2];
    const float* Wv    = (const float*)d_in[3];
    const float* bq    = (const float*)d_in[4];
    const float* bk    = (const float*)d_in[5];
    const float* bv    = (const float*)d_in[6];
    const float* Wo    = (const float*)d_in[7];
    const float* bo    = (const float*)d_in[8];
    float* out = (float*)d_out;

    float *qp, *kp, *vp, *mp;
    cudaGetSymbolAddress((void**)&qp, g_Q);
    cudaGetSymbolAddress((void**)&kp, g_K);
    cudaGetSymbolAddress((void**)&vp, g_V);
    cudaGetSymbolAddress((void**)&mp, g_M);

    static bool attr_set = false;
    if (!attr_set) {
        cudaFuncSetAttribute(attn_kernel,
                             cudaFuncAttributeMaxDynamicSharedMemorySize,
                             ATTN_SMEM_BYTES);
        attr_set = true;
    }

    dim3 gthreads(256);
    dim3 ggrid(DM / 64, NROWS / 64);   // (8, 128)

    // QKV projections
    gemm_bias_kernel<<<ggrid, gthreads>>>(nodes, Wq, bq, qp, NROWS, DM, DM);
    gemm_bias_kernel<<<ggrid, gthreads>>>(nodes, Wk, bk, kp, NROWS, DM, DM);
    gemm_bias_kernel<<<ggrid, gthreads>>>(nodes, Wv, bv, vp, NROWS, DM, DM);

    // Attention
    dim3 agrid(S_ / 64, B_ * H_);      // (16, 64)
    attn_kernel<<<agrid, 256, ATTN_SMEM_BYTES>>>();

    // Output projection
    gemm_bias_kernel<<<ggrid, gthreads>>>(mp, Wo, bo, out, NROWS, DM, DM);
}

// round 14
// speedup vs baseline: 3.0430x; 3.0430x over previous
#include <cuda_runtime.h>
#include <math.h>
#include <stdint.h>

#define B_  8
#define S_  1024
#define DM  512
#define H_  8
#define DK  64
#define NROWS (B_ * S_)   // 8192

// Scratch (allocation-free rule: __device__ globals)
__device__ float g_Q[NROWS * DM];
__device__ float g_K[NROWS * DM];
__device__ float g_V[NROWS * DM];
__device__ float g_M[NROWS * DM];

__device__ __forceinline__ float cvt_tf32(float x) {
    unsigned u;
    asm("cvt.rna.tf32.f32 %0, %1;" : "=r"(u) : "f"(x));
    return __uint_as_float(u);
}
__device__ __forceinline__ unsigned fu(float x) { return __float_as_uint(x); }

__device__ __forceinline__ void mma_tf32(float* c, const unsigned* a, const unsigned* b) {
    asm volatile(
        "mma.sync.aligned.m16n8k8.row.col.f32.tf32.tf32.f32 "
        "{%0,%1,%2,%3}, {%4,%5,%6,%7}, {%8,%9}, {%0,%1,%2,%3};\n"
        : "+f"(c[0]), "+f"(c[1]), "+f"(c[2]), "+f"(c[3])
        : "r"(a[0]), "r"(a[1]), "r"(a[2]), "r"(a[3]), "r"(b[0]), "r"(b[1]));
}

// ---------------------------------------------------------------------------
// tf32 GEMM: C[M,N] = A[M,K] @ B[K,N] + bias.  CTA tile 128x128, BK=32.
// 256 threads = 8 warps (2M x 4N), warp tile 64x32 (4 m-tiles x 4 n-tiles).
// As: [m][k] stride 36  (rows are 32 wide -> in-bounds; frag bank 4g+t)
// Bs: [k][n] stride 136 (rows are 128 wide; frag bank 8t+g)
// ---------------------------------------------------------------------------
__global__ __launch_bounds__(256, 2) void gemm_tf32_kernel(
    const float* __restrict__ A, const float* __restrict__ Bm,
    const float* __restrict__ bias, float* __restrict__ C,
    int M, int N, int K)
{
    __shared__ float As[128 * 36];
    __shared__ float Bs[32 * 136];

    const int tid  = threadIdx.x;
    const int lane = tid & 31;
    const int warp = tid >> 5;
    const int g = lane >> 2;
    const int t = lane & 3;
    const int wm0 = (warp >> 2) * 64;   // 0 or 64
    const int wn0 = (warp & 3) * 32;    // 0,32,64,96
    const int bm0 = blockIdx.y * 128;
    const int bn0 = blockIdx.x * 128;

    float acc[4][4][4];
#pragma unroll
    for (int i = 0; i < 4; i++)
#pragma unroll
        for (int j = 0; j < 4; j++)
#pragma unroll
            for (int r = 0; r < 4; r++) acc[i][j][r] = 0.f;

    for (int k0 = 0; k0 < K; k0 += 32) {
        // A tile: 128 x 32 -> As[m][k]
#pragma unroll
        for (int it = 0; it < 4; it++) {
            int f = tid + it * 256;
            int m = f >> 3, kq = f & 7;
            float4 v = *(const float4*)&A[(size_t)(bm0 + m) * K + k0 + kq * 4];
            As[m * 36 + kq * 4 + 0] = cvt_tf32(v.x);
            As[m * 36 + kq * 4 + 1] = cvt_tf32(v.y);
            As[m * 36 + kq * 4 + 2] = cvt_tf32(v.z);
            As[m * 36 + kq * 4 + 3] = cvt_tf32(v.w);
        }
        // B tile: 32 x 128 -> Bs[k][n]
#pragma unroll
        for (int it = 0; it < 4; it++) {
            int f = tid + it * 256;
            int k = f >> 5, nq = f & 31;
            float4 v = *(const float4*)&Bm[(size_t)(k0 + k) * N + bn0 + nq * 4];
            float4 w;
            w.x = cvt_tf32(v.x); w.y = cvt_tf32(v.y);
            w.z = cvt_tf32(v.z); w.w = cvt_tf32(v.w);
            *(float4*)&Bs[k * 136 + nq * 4] = w;
        }
        __syncthreads();

#pragma unroll
        for (int kk = 0; kk < 4; kk++) {
            unsigned a[4][4], b[4][2];
#pragma unroll
            for (int tm = 0; tm < 4; tm++) {
                int r0 = (wm0 + tm * 16 + g) * 36 + kk * 8 + t;
                int r1 = (wm0 + tm * 16 + g + 8) * 36 + kk * 8 + t;
                a[tm][0] = fu(As[r0]);
                a[tm][1] = fu(As[r1]);
                a[tm][2] = fu(As[r0 + 4]);
                a[tm][3] = fu(As[r1 + 4]);
            }
#pragma unroll
            for (int tn = 0; tn < 4; tn++) {
                int c0 = (kk * 8 + t) * 136 + wn0 + tn * 8 + g;
                b[tn][0] = fu(Bs[c0]);
                b[tn][1] = fu(Bs[c0 + 4 * 136]);
            }
#pragma unroll
            for (int tm = 0; tm < 4; tm++)
#pragma unroll
                for (int tn = 0; tn < 4; tn++)
                    mma_tf32(acc[tm][tn], a[tm], b[tn]);
        }
        __syncthreads();
    }

#pragma unroll
    for (int tm = 0; tm < 4; tm++) {
        int r0 = bm0 + wm0 + tm * 16 + g;
#pragma unroll
        for (int tn = 0; tn < 4; tn++) {
            int c = bn0 + wn0 + tn * 8 + 2 * t;
            float b0 = bias[c], b1 = bias[c + 1];
            float2 v0 = make_float2(acc[tm][tn][0] + b0, acc[tm][tn][1] + b1);
            float2 v1 = make_float2(acc[tm][tn][2] + b0, acc[tm][tn][3] + b1);
            *(float2*)&C[(size_t)r0 * N + c]       = v0;
            *(float2*)&C[(size_t)(r0 + 8) * N + c] = v1;
        }
    }
}

// ---------------------------------------------------------------------------
// tf32 flash attention. CTA = 128 q-rows of one (b,h). 8 warps, 16 q-rows each.
// Rows are 64 elements wide -> strides must be >= 64:
//   Qs/Ks/Pw stride 68 (68 mod 32 = 4 -> A-frag banks 4g+t distinct)
//   Vs stride 72       (72 mod 32 = 8 -> B-frag banks 8t+g distinct)
// Smem (floats): Qs 128*68 | Ks 64*68 | Vs 64*72 | Pw 8*16*68  = 26368 (103KB)
// ---------------------------------------------------------------------------
#define QS_STR 68
#define KS_STR 68
#define VS_STR 72
#define PW_STR 68
#define AQ_OFF 0
#define AK_OFF (128 * QS_STR)
#define AV_OFF (AK_OFF + 64 * KS_STR)
#define AP_OFF (AV_OFF + 64 * VS_STR)
#define ATTN_SMEM_FLOATS (AP_OFF + 8 * 16 * PW_STR)
#define ATTN_SMEM_BYTES (ATTN_SMEM_FLOATS * 4)

__global__ __launch_bounds__(256, 1) void attn_tf32_kernel()
{
    extern __shared__ float sm[];
    float* Qs = sm + AQ_OFF;
    float* Ks = sm + AK_OFF;
    float* Vs = sm + AV_OFF;

    const int tid  = threadIdx.x;
    const int lane = tid & 31;
    const int warp = tid >> 5;
    const int g = lane >> 2;
    const int t = lane & 3;
    const int wq0 = warp * 16;
    float* Pw = sm + AP_OFF + warp * (16 * PW_STR);

    const int bh = blockIdx.y;
    const int b  = bh / H_;
    const int h  = bh % H_;
    const int q0 = blockIdx.x * 128;

    // Load Q tile (pre-scaled by 1/sqrt(dk), tf32-converted)
#pragma unroll
    for (int it = 0; it < 8; it++) {
        int f = tid + it * 256;
        int q = f >> 4, dq = f & 15;
        float4 v = *(const float4*)&g_Q[(size_t)(b * S_ + q0 + q) * DM + h * DK + dq * 4];
        Qs[q * QS_STR + dq * 4 + 0] = cvt_tf32(v.x * 0.125f);
        Qs[q * QS_STR + dq * 4 + 1] = cvt_tf32(v.y * 0.125f);
        Qs[q * QS_STR + dq * 4 + 2] = cvt_tf32(v.z * 0.125f);
        Qs[q * QS_STR + dq * 4 + 3] = cvt_tf32(v.w * 0.125f);
    }
    __syncthreads();

    // Register-cache Q fragments: 8 k-steps x 4 regs
    unsigned qa[8][4];
#pragma unroll
    for (int kk = 0; kk < 8; kk++) {
        int r0 = (wq0 + g) * QS_STR + kk * 8 + t;
        int r1 = (wq0 + g + 8) * QS_STR + kk * 8 + t;
        qa[kk][0] = fu(Qs[r0]);
        qa[kk][1] = fu(Qs[r1]);
        qa[kk][2] = fu(Qs[r0 + 4]);
        qa[kk][3] = fu(Qs[r1 + 4]);
    }

    float o[8][4];
#pragma unroll
    for (int tn = 0; tn < 8; tn++)
#pragma unroll
        for (int r = 0; r < 4; r++) o[tn][r] = 0.f;
    float m0 = -1e30f, m1 = -1e30f, l0 = 0.f, l1 = 0.f;

    for (int kt = 0; kt < S_ / 64; kt++) {
        const int t0 = kt * 64;
        // K tile -> Ks[key][d]
#pragma unroll
        for (int it = 0; it < 4; it++) {
            int f = tid + it * 256;
            int key = f >> 4, dq = f & 15;
            float4 v = *(const float4*)&g_K[(size_t)(b * S_ + t0 + key) * DM + h * DK + dq * 4];
            Ks[key * KS_STR + dq * 4 + 0] = cvt_tf32(v.x);
            Ks[key * KS_STR + dq * 4 + 1] = cvt_tf32(v.y);
            Ks[key * KS_STR + dq * 4 + 2] = cvt_tf32(v.z);
            Ks[key * KS_STR + dq * 4 + 3] = cvt_tf32(v.w);
        }
        // V tile -> Vs[key][d] (float4 stores)
#pragma unroll
        for (int it = 0; it < 4; it++) {
            int f = tid + it * 256;
            int key = f >> 4, dq = f & 15;
            float4 v = *(const float4*)&g_V[(size_t)(b * S_ + t0 + key) * DM + h * DK + dq * 4];
            float4 w;
            w.x = cvt_tf32(v.x); w.y = cvt_tf32(v.y);
            w.z = cvt_tf32(v.z); w.w = cvt_tf32(v.w);
            *(float4*)&Vs[key * VS_STR + dq * 4] = w;
        }
        __syncthreads();

        // S = Q @ K^T  : 8 n-tiles (keys) x 8 k-steps (d)
        float s[8][4];
#pragma unroll
        for (int tn = 0; tn < 8; tn++)
#pragma unroll
            for (int r = 0; r < 4; r++) s[tn][r] = 0.f;
#pragma unroll
        for (int kk = 0; kk < 8; kk++) {
#pragma unroll
            for (int tn = 0; tn < 8; tn++) {
                unsigned bfr[2];
                int c0 = (tn * 8 + g) * KS_STR + kk * 8 + t;
                bfr[0] = fu(Ks[c0]);
                bfr[1] = fu(Ks[c0 + 4]);
                mma_tf32(s[tn], qa[kk], bfr);
            }
        }

        // Online softmax (Q pre-scaled). Rows: g (regs 0,1) and g+8 (regs 2,3).
        float mx0 = -1e30f, mx1 = -1e30f;
#pragma unroll
        for (int tn = 0; tn < 8; tn++) {
            mx0 = fmaxf(mx0, fmaxf(s[tn][0], s[tn][1]));
            mx1 = fmaxf(mx1, fmaxf(s[tn][2], s[tn][3]));
        }
#pragma unroll
        for (int ofs = 1; ofs <= 2; ofs <<= 1) {
            mx0 = fmaxf(mx0, __shfl_xor_sync(0xffffffffu, mx0, ofs));
            mx1 = fmaxf(mx1, __shfl_xor_sync(0xffffffffu, mx1, ofs));
        }
        float mn0 = fmaxf(m0, mx0), mn1 = fmaxf(m1, mx1);
        float al0 = __expf(m0 - mn0), al1 = __expf(m1 - mn1);
        m0 = mn0; m1 = mn1;
        float rs0 = 0.f, rs1 = 0.f;
#pragma unroll
        for (int tn = 0; tn < 8; tn++) {
            s[tn][0] = __expf(s[tn][0] - mn0);
            s[tn][1] = __expf(s[tn][1] - mn0);
            s[tn][2] = __expf(s[tn][2] - mn1);
            s[tn][3] = __expf(s[tn][3] - mn1);
            rs0 += s[tn][0] + s[tn][1];
            rs1 += s[tn][2] + s[tn][3];
        }
#pragma unroll
        for (int ofs = 1; ofs <= 2; ofs <<= 1) {
            rs0 += __shfl_xor_sync(0xffffffffu, rs0, ofs);
            rs1 += __shfl_xor_sync(0xffffffffu, rs1, ofs);
        }
        l0 = l0 * al0 + rs0;
        l1 = l1 * al1 + rs1;
#pragma unroll
        for (int tn = 0; tn < 8; tn++) {
            o[tn][0] *= al0; o[tn][1] *= al0;
            o[tn][2] *= al1; o[tn][3] *= al1;
            // stage P (tf32) into per-warp smem
            Pw[g * PW_STR + tn * 8 + 2 * t]           = cvt_tf32(s[tn][0]);
            Pw[g * PW_STR + tn * 8 + 2 * t + 1]       = cvt_tf32(s[tn][1]);
            Pw[(g + 8) * PW_STR + tn * 8 + 2 * t]     = cvt_tf32(s[tn][2]);
            Pw[(g + 8) * PW_STR + tn * 8 + 2 * t + 1] = cvt_tf32(s[tn][3]);
        }
        __syncwarp();

        // O += P @ V : 8 k-steps (keys) x 8 n-tiles (d)
#pragma unroll
        for (int kk = 0; kk < 8; kk++) {
            unsigned a[4];
            int r0 = g * PW_STR + kk * 8 + t;
            int r1 = (g + 8) * PW_STR + kk * 8 + t;
            a[0] = fu(Pw[r0]);
            a[1] = fu(Pw[r1]);
            a[2] = fu(Pw[r0 + 4]);
            a[3] = fu(Pw[r1 + 4]);
#pragma unroll
            for (int tn = 0; tn < 8; tn++) {
                unsigned bfr[2];
                int c0 = (kk * 8 + t) * VS_STR + tn * 8 + g;
                bfr[0] = fu(Vs[c0]);
                bfr[1] = fu(Vs[c0 + 4 * VS_STR]);
                mma_tf32(o[tn], a, bfr);
            }
        }
        __syncthreads();   // protect Ks/Vs before next tile's stores
    }

    // Normalize + write msgs
    float inv0 = 1.f / l0, inv1 = 1.f / l1;
    int row0 = b * S_ + q0 + wq0 + g;
#pragma unroll
    for (int tn = 0; tn < 8; tn++) {
        int c = h * DK + tn * 8 + 2 * t;
        float2 v0 = make_float2(o[tn][0] * inv0, o[tn][1] * inv0);
        float2 v1 = make_float2(o[tn][2] * inv1, o[tn][3] * inv1);
        *(float2*)&g_M[(size_t)row0 * DM + c]       = v0;
        *(float2*)&g_M[(size_t)(row0 + 8) * DM + c] = v1;
    }
}

// ---------------------------------------------------------------------------
extern "C" void kernel_launch(void* const* d_in, const int* in_sizes, int n_in,
                              void* d_out, int out_size)
{
    const float* nodes = (const float*)d_in[0];
    const float* Wq    = (const float*)d_in[1];
    const float* Wk    = (const float*)d_in[2];
    const float* Wv    = (const float*)d_in[3];
    const float* bq    = (const float*)d_in[4];
    const float* bk    = (const float*)d_in[5];
    const float* bv    = (const float*)d_in[6];
    const float* Wo    = (const float*)d_in[7];
    const float* bo    = (const float*)d_in[8];
    float* out = (float*)d_out;

    float *qp, *kp, *vp, *mp;
    cudaGetSymbolAddress((void**)&qp, g_Q);
    cudaGetSymbolAddress((void**)&kp, g_K);
    cudaGetSymbolAddress((void**)&vp, g_V);
    cudaGetSymbolAddress((void**)&mp, g_M);

    static bool attr_set = false;
    if (!attr_set) {
        cudaFuncSetAttribute(attn_tf32_kernel,
                             cudaFuncAttributeMaxDynamicSharedMemorySize,
                             ATTN_SMEM_BYTES);
        attr_set = true;
    }

    dim3 gthreads(256);
    dim3 ggrid(DM / 128, NROWS / 128);   // (4, 64)

    gemm_tf32_kernel<<<ggrid, gthreads>>>(nodes, Wq, bq, qp, NROWS, DM, DM);
    gemm_tf32_kernel<<<ggrid, gthreads>>>(nodes, Wk, bk, kp, NROWS, DM, DM);
    gemm_tf32_kernel<<<ggrid, gthreads>>>(nodes, Wv, bv, vp, NROWS, DM, DM);

    dim3 agrid(S_ / 128, B_ * H_);       // (8, 64)
    attn_tf32_kernel<<<agrid, 256, ATTN_SMEM_BYTES>>>();

    gemm_tf32_kernel<<<ggrid, gthreads>>>(mp, Wo, bo, out, NROWS, DM, DM);
}